// round 1
// baseline (speedup 1.0000x reference)
#include <cuda_runtime.h>
#include <cuda_bf16.h>
#include <math.h>

#define Bx 4
#define T 1024
#define D 512
#define H 8
#define DH 64
#define W1 32
#define WB 65
#define FF 2048
#define CE 1024
#define KS 31
#define NTOK (Bx*T)
#define EPS 1e-5f

// ---------------- scratch (static device globals; no allocation) ----------------
__device__ __align__(16) float g_xln[NTOK*D];
__device__ __align__(16) float g_ff [NTOK*FF];
__device__ __align__(16) float g_h  [NTOK*D];
__device__ __align__(16) float g_q  [NTOK*D];
__device__ __align__(16) float g_k  [NTOK*D];
__device__ __align__(16) float g_v  [NTOK*D];
__device__ __align__(16) float g_cf [NTOK*CE];
__device__ __align__(16) float g_u  [NTOK*D];
__device__ __align__(16) float g_v2 [NTOK*D];

// ---------------- LayerNorm: one block (128 thr) per row of 512 ----------------
__device__ __forceinline__ float warpSum(float v){
    #pragma unroll
    for (int o=16;o;o>>=1) v += __shfl_xor_sync(0xffffffffu, v, o);
    return v;
}

__global__ void ln_kernel(const float* __restrict__ X, const float* __restrict__ gam,
                          const float* __restrict__ bet, float* __restrict__ Y){
    int row = blockIdx.x;
    int tid = threadIdx.x;                      // 128 threads, 4 floats each
    const float4* x4 = (const float4*)(X + (size_t)row*D);
    float4 v = x4[tid];
    float s  = v.x+v.y+v.z+v.w;
    float ss = v.x*v.x+v.y*v.y+v.z*v.z+v.w*v.w;
    __shared__ float red[8];
    s = warpSum(s); ss = warpSum(ss);
    int wid = tid>>5, lane = tid&31;
    if (lane==0){ red[wid]=s; red[4+wid]=ss; }
    __syncthreads();
    if (tid==0){
        float ts  = red[0]+red[1]+red[2]+red[3];
        float tss = red[4]+red[5]+red[6]+red[7];
        float mean = ts*(1.0f/D);
        float var  = tss*(1.0f/D) - mean*mean;
        red[0]=mean; red[1]=rsqrtf(var + EPS);
    }
    __syncthreads();
    float mean = red[0], rstd = red[1];
    float4 g = ((const float4*)gam)[tid];
    float4 b = ((const float4*)bet)[tid];
    float4 o;
    o.x=(v.x-mean)*rstd*g.x+b.x; o.y=(v.y-mean)*rstd*g.y+b.y;
    o.z=(v.z-mean)*rstd*g.z+b.z; o.w=(v.w-mean)*rstd*g.w+b.w;
    ((float4*)(Y + (size_t)row*D))[tid]=o;
}

// ---------------- SGEMM 128x128x8, 8x8/thread, fused epilogues ----------------
// MODE: 0 = C=AW+bias ; 1 = swish(AW+bias) ; 2 = C=R+alpha*(AW+bias) ; 3 = alpha*(AW+bias)
template<int MODE>
__global__ __launch_bounds__(256) void sgemm_kernel(
    const float* __restrict__ A, const float* __restrict__ W,
    const float* __restrict__ bias, const float* __restrict__ R,
    float* __restrict__ C, int M, int N, int K, float alpha)
{
    __shared__ float As[8][132];
    __shared__ float Bs[8][132];
    const int tid = threadIdx.x;
    const int bx = blockIdx.x, by = blockIdx.y;
    const int tx = tid & 15, ty = tid >> 4;
    const float* Ab = A + (size_t)by*128*K;
    const float* Wb = W + bx*128;
    const int aRow = tid >> 1, aCol = (tid & 1)*4;
    const int bRow = tid >> 5, bCol = (tid & 31)*4;
    float acc[8][8] = {};
    for (int k0 = 0; k0 < K; k0 += 8){
        float4 a4 = *(const float4*)(Ab + (size_t)aRow*K + k0 + aCol);
        As[aCol+0][aRow]=a4.x; As[aCol+1][aRow]=a4.y;
        As[aCol+2][aRow]=a4.z; As[aCol+3][aRow]=a4.w;
        float4 b4 = *(const float4*)(Wb + (size_t)(k0+bRow)*N + bCol);
        Bs[bRow][bCol+0]=b4.x; Bs[bRow][bCol+1]=b4.y;
        Bs[bRow][bCol+2]=b4.z; Bs[bRow][bCol+3]=b4.w;
        __syncthreads();
        #pragma unroll
        for (int k=0;k<8;k++){
            float rm[8], rn[8];
            #pragma unroll
            for (int i=0;i<8;i++) rm[i]=As[k][ty*8+i];
            #pragma unroll
            for (int j=0;j<8;j++) rn[j]=Bs[k][tx*8+j];
            #pragma unroll
            for (int i=0;i<8;i++)
                #pragma unroll
                for (int j=0;j<8;j++) acc[i][j] = fmaf(rm[i], rn[j], acc[i][j]);
        }
        __syncthreads();
    }
    #pragma unroll
    for (int i=0;i<8;i++){
        size_t row = (size_t)by*128 + ty*8 + i;
        #pragma unroll
        for (int j=0;j<8;j++){
            int col = bx*128 + tx*8 + j;
            float v = acc[i][j] + bias[col];
            if (MODE==1) v = v / (1.0f + expf(-v));
            if (MODE==3) v = alpha * v;
            if (MODE==2) v = R[row*(size_t)N + col] + alpha * v;
            C[row*(size_t)N + col] = v;
        }
    }
}

// ---------------- banded attention: warp per (b,t,h); h += ctx in place ----------------
__global__ void attn_kernel(const float* __restrict__ Q, const float* __restrict__ Kt,
                            const float* __restrict__ V, float* __restrict__ Hh,
                            float* __restrict__ P){
    __shared__ float sc[8][WB+7];
    int warp = threadIdx.x >> 5;
    int lane = threadIdx.x & 31;
    int wg = blockIdx.x*8 + warp;          // 0 .. B*T*H-1
    int h = wg & (H-1);
    int t = (wg >> 3) & (T-1);
    int b = wg >> 13;
    size_t base = ((size_t)(b*T + t))*D + h*DH;
    int d0 = lane*2;
    float q0 = Q[base + d0], q1 = Q[base + d0 + 1];
    float* s = sc[warp];
    for (int w=0; w<WB; w++){
        int src = t - W1 + w;
        float sv = -1e9f;
        if ((unsigned)src < (unsigned)T){
            size_t kb = ((size_t)(b*T + src))*D + h*DH;
            float p = q0*Kt[kb+d0] + q1*Kt[kb+d0+1];
            #pragma unroll
            for (int o=16;o;o>>=1) p += __shfl_xor_sync(0xffffffffu, p, o);
            sv = p;
        }
        if (lane==0) s[w] = sv;
    }
    __syncwarp();
    float m = -1e30f;
    for (int w=lane; w<WB; w+=32) m = fmaxf(m, s[w]);
    #pragma unroll
    for (int o=16;o;o>>=1) m = fmaxf(m, __shfl_xor_sync(0xffffffffu, m, o));
    float sum = 0.0f;
    for (int w=lane; w<WB; w+=32){ float e = expf(s[w]-m); s[w]=e; sum+=e; }
    #pragma unroll
    for (int o=16;o;o>>=1) sum += __shfl_xor_sync(0xffffffffu, sum, o);
    float inv = 1.0f/sum;
    __syncwarp();
    float* pp = P + ((size_t)((b*T + t)*H + h))*WB;
    for (int w=lane; w<WB; w+=32) pp[w] = s[w]*inv;
    float a0=0.0f, a1=0.0f;
    for (int w=0; w<WB; w++){
        int src = t - W1 + w;
        if ((unsigned)src >= (unsigned)T) continue;
        float p = s[w]*inv;
        size_t vb = ((size_t)(b*T + src))*D + h*DH;
        a0 += p*V[vb+d0];
        a1 += p*V[vb+d0+1];
    }
    Hh[base+d0]   += a0;
    Hh[base+d0+1] += a1;
}

// ---------------- GLU: u = a * sigmoid(gate) ----------------
__global__ void glu_kernel(const float* __restrict__ CF, float* __restrict__ U){
    int idx = blockIdx.x*blockDim.x + threadIdx.x;     // NTOK*D
    int r = idx >> 9;
    int c = idx & (D-1);
    float a = CF[(size_t)r*CE + c];
    float g = CF[(size_t)r*CE + D + c];
    U[idx] = a / (1.0f + expf(-g));
}

// ---------------- depthwise conv (K=31) + bn + swish ----------------
__global__ void dwconv_kernel(const float* __restrict__ U, const float* __restrict__ Wd,
                              const float* __restrict__ bd, const float* __restrict__ bg,
                              const float* __restrict__ bb, float* __restrict__ O){
    int idx = blockIdx.x*blockDim.x + threadIdx.x;     // NTOK*D
    int c = idx & (D-1);
    int tt = idx >> 9;
    int t = tt & (T-1);
    int b = tt >> 10;
    float acc = bd[c];
    #pragma unroll
    for (int k=0;k<KS;k++){
        int src = t - (KS-1)/2 + k;
        if ((unsigned)src < (unsigned)T)
            acc = fmaf(U[((size_t)(b*T+src))*D + c], Wd[k*D + c], acc);
    }
    const float bns = 0.99999500003749937f;            // rsqrt(1+1e-5)
    acc = acc*bns*bg[c] + bb[c];
    O[idx] = acc / (1.0f + expf(-acc));                // swish
}

// ---------------- host ----------------
static float* symaddr(const void* s){
    void* p = nullptr;
    cudaGetSymbolAddress(&p, s);
    return (float*)p;
}

extern "C" void kernel_launch(void* const* d_in, const int* in_sizes, int n_in,
                              void* d_out, int out_size){
    const float* x         = (const float*)d_in[0];
    const float* ff1_ln_g  = (const float*)d_in[1];
    const float* ff1_ln_b  = (const float*)d_in[2];
    const float* ff1_w1    = (const float*)d_in[3];
    const float* ff1_b1    = (const float*)d_in[4];
    const float* ff1_w2    = (const float*)d_in[5];
    const float* ff1_b2    = (const float*)d_in[6];
    const float* ff2_ln_g  = (const float*)d_in[7];
    const float* ff2_ln_b  = (const float*)d_in[8];
    const float* ff2_w1    = (const float*)d_in[9];
    const float* ff2_b1    = (const float*)d_in[10];
    const float* ff2_w2    = (const float*)d_in[11];
    const float* ff2_b2    = (const float*)d_in[12];
    const float* wq        = (const float*)d_in[13];
    const float* bq        = (const float*)d_in[14];
    const float* wk        = (const float*)d_in[15];
    const float* bk        = (const float*)d_in[16];
    const float* wv        = (const float*)d_in[17];
    const float* bv        = (const float*)d_in[18];
    const float* conv_ln_g = (const float*)d_in[19];
    const float* conv_ln_b = (const float*)d_in[20];
    const float* pw1_w     = (const float*)d_in[21];
    const float* pw1_b     = (const float*)d_in[22];
    const float* dw_w      = (const float*)d_in[23];
    const float* dw_b      = (const float*)d_in[24];
    const float* bn_g      = (const float*)d_in[25];
    const float* bn_b      = (const float*)d_in[26];
    const float* pw2_w     = (const float*)d_in[27];
    const float* pw2_b     = (const float*)d_in[28];
    const float* fin_ln_g  = (const float*)d_in[29];
    const float* fin_ln_b  = (const float*)d_in[30];

    float* out   = (float*)d_out;
    float* probs = out + (size_t)NTOK*D;

    float* xln = symaddr(g_xln);
    float* ff  = symaddr(g_ff);
    float* h   = symaddr(g_h);
    float* q   = symaddr(g_q);
    float* k   = symaddr(g_k);
    float* v   = symaddr(g_v);
    float* cf  = symaddr(g_cf);
    float* u   = symaddr(g_u);
    float* v2  = symaddr(g_v2);

    const int M = NTOK;
    dim3 blk(256);

    // ---- ff1 (half-scale residual) ----
    ln_kernel<<<M,128>>>(x, ff1_ln_g, ff1_ln_b, xln);
    sgemm_kernel<1><<<dim3(FF/128, M/128), blk>>>(xln, ff1_w1, ff1_b1, nullptr, ff, M, FF, D, 1.0f);
    sgemm_kernel<2><<<dim3(D/128,  M/128), blk>>>(ff,  ff1_w2, ff1_b2, x,       h,  M, D, FF, 0.5f);

    // ---- QKV ----
    sgemm_kernel<3><<<dim3(D/128, M/128), blk>>>(h, wq, bq, nullptr, q, M, D, D, 0.125f); // 1/sqrt(64)
    sgemm_kernel<0><<<dim3(D/128, M/128), blk>>>(h, wk, bk, nullptr, k, M, D, D, 1.0f);
    sgemm_kernel<0><<<dim3(D/128, M/128), blk>>>(h, wv, bv, nullptr, v, M, D, D, 1.0f);

    // ---- banded attention (h += ctx in place; writes probs) ----
    attn_kernel<<<(Bx*T*H)/8, 256>>>(q, k, v, h, probs);

    // ---- conv module (residual in place) ----
    ln_kernel<<<M,128>>>(h, conv_ln_g, conv_ln_b, xln);
    sgemm_kernel<0><<<dim3(CE/128, M/128), blk>>>(xln, pw1_w, pw1_b, nullptr, cf, M, CE, D, 1.0f);
    glu_kernel<<<(NTOK*D)/256, 256>>>(cf, u);
    dwconv_kernel<<<(NTOK*D)/256, 256>>>(u, dw_w, dw_b, bn_g, bn_b, v2);
    sgemm_kernel<2><<<dim3(D/128, M/128), blk>>>(v2, pw2_w, pw2_b, h, h, M, D, D, 1.0f);

    // ---- ff2 (half-scale residual, in place) ----
    ln_kernel<<<M,128>>>(h, ff2_ln_g, ff2_ln_b, xln);
    sgemm_kernel<1><<<dim3(FF/128, M/128), blk>>>(xln, ff2_w1, ff2_b1, nullptr, ff, M, FF, D, 1.0f);
    sgemm_kernel<2><<<dim3(D/128,  M/128), blk>>>(ff,  ff2_w2, ff2_b2, h,       h,  M, D, FF, 0.5f);

    // ---- final LN straight into d_out ----
    ln_kernel<<<M,128>>>(h, fin_ln_g, fin_ln_b, out);
}

// round 3
// speedup vs baseline: 2.9420x; 2.9420x over previous
#include <cuda_runtime.h>
#include <cuda_bf16.h>
#include <math.h>
#include <stdint.h>

#define Bx 4
#define T 1024
#define D 512
#define H 8
#define DH 64
#define W1 32
#define WB 65
#define FF 2048
#define CE 1024
#define KS 31
#define NTOK (Bx*T)
#define EPS 1e-5f

// ---------------- scratch (static device globals; no allocation) ----------------
__device__ __align__(16) float g_xln[NTOK*D];
__device__ __align__(16) float g_ff [NTOK*FF];
__device__ __align__(16) float g_h  [NTOK*D];
__device__ __align__(16) float g_q  [NTOK*D];
__device__ __align__(16) float g_k  [NTOK*D];
__device__ __align__(16) float g_v  [NTOK*D];
__device__ __align__(16) float g_cf [NTOK*CE];
__device__ __align__(16) float g_u  [NTOK*D];
__device__ __align__(16) float g_v2 [NTOK*D];

// ---------------- small PTX helpers ----------------
__device__ __forceinline__ uint32_t f2tf(float f){
    uint32_t u; asm("cvt.rna.tf32.f32 %0, %1;" : "=r"(u) : "f"(f)); return u;
}
__device__ __forceinline__ void mma_tf32(float* c, const uint32_t* a, const uint32_t* b){
    asm volatile(
        "mma.sync.aligned.m16n8k8.row.col.f32.tf32.tf32.f32 "
        "{%0,%1,%2,%3}, {%4,%5,%6,%7}, {%8,%9}, {%0,%1,%2,%3};"
        : "+f"(c[0]), "+f"(c[1]), "+f"(c[2]), "+f"(c[3])
        : "r"(a[0]), "r"(a[1]), "r"(a[2]), "r"(a[3]), "r"(b[0]), "r"(b[1]));
}
__device__ __forceinline__ void cpasync16(void* smem, const void* g){
    uint32_t s = (uint32_t)__cvta_generic_to_shared(smem);
    asm volatile("cp.async.cg.shared.global [%0], [%1], 16;" :: "r"(s), "l"(g));
}
__device__ __forceinline__ void cp_commit(){ asm volatile("cp.async.commit_group;"); }
template<int N> __device__ __forceinline__ void cp_wait(){ asm volatile("cp.async.wait_group %0;" :: "n"(N)); }

// ---------------- LayerNorm: one block (128 thr) per row of 512 ----------------
__device__ __forceinline__ float warpSum(float v){
    #pragma unroll
    for (int o=16;o;o>>=1) v += __shfl_xor_sync(0xffffffffu, v, o);
    return v;
}

__global__ void ln_kernel(const float* __restrict__ X, const float* __restrict__ gam,
                          const float* __restrict__ bet, float* __restrict__ Y){
    int row = blockIdx.x;
    int tid = threadIdx.x;                      // 128 threads, 4 floats each
    const float4* x4 = (const float4*)(X + (size_t)row*D);
    float4 v = x4[tid];
    float s  = v.x+v.y+v.z+v.w;
    float ss = v.x*v.x+v.y*v.y+v.z*v.z+v.w*v.w;
    __shared__ float red[8];
    s = warpSum(s); ss = warpSum(ss);
    int wid = tid>>5, lane = tid&31;
    if (lane==0){ red[wid]=s; red[4+wid]=ss; }
    __syncthreads();
    if (tid==0){
        float ts  = red[0]+red[1]+red[2]+red[3];
        float tss = red[4]+red[5]+red[6]+red[7];
        float mean = ts*(1.0f/D);
        float var  = tss*(1.0f/D) - mean*mean;
        red[0]=mean; red[1]=rsqrtf(var + EPS);
    }
    __syncthreads();
    float mean = red[0], rstd = red[1];
    float4 g = ((const float4*)gam)[tid];
    float4 b = ((const float4*)bet)[tid];
    float4 o;
    o.x=(v.x-mean)*rstd*g.x+b.x; o.y=(v.y-mean)*rstd*g.y+b.y;
    o.z=(v.z-mean)*rstd*g.z+b.z; o.w=(v.w-mean)*rstd*g.w+b.w;
    ((float4*)(Y + (size_t)row*D))[tid]=o;
}

// ---------------- TF32 tensor-core GEMM 128x128, BK=16, warp 64x32 ----------------
// MODE: 0 = C=AW+bias ; 1 = swish(AW+bias) ; 2 = C=R+alpha*(AW+bias) ; 3 = alpha*(AW+bias)
#define ASTRIDE 20   // BK(16)+4 pad  -> conflict-free A frag loads
#define BSTRIDE 136  // BN(128)+8 pad -> conflict-free B frag loads

template<int MODE>
__global__ __launch_bounds__(256, 2) void tgemm_kernel(
    const float* __restrict__ A, const float* __restrict__ W,
    const float* __restrict__ bias, const float* __restrict__ R,
    float* __restrict__ C, int M, int N, int K, float alpha)
{
    __shared__ float As[2][128*ASTRIDE];
    __shared__ float Bs[2][16*BSTRIDE];

    const int tid  = threadIdx.x;
    const int lane = tid & 31;
    const int wid  = tid >> 5;
    const int wm   = wid >> 2;        // 0..1  (64 rows each)
    const int wn   = wid & 3;         // 0..3  (32 cols each)
    const int bx = blockIdx.x, by = blockIdx.y;

    // global load assignments
    const int aRow  = tid >> 2;              // 0..63 (+64)
    const int aCol4 = (tid & 3) * 4;         // 0,4,8,12
    const int bRow  = tid >> 5;              // 0..7 (+8)
    const int bCol4 = (tid & 31) * 4;        // 0..124

    const float* Ag = A + (size_t)(by*128 + aRow)*K + aCol4;
    const float* Bg = W + (size_t)bRow*N + bx*128 + bCol4;

    float acc[4][4][4];
    #pragma unroll
    for (int i=0;i<4;i++)
        #pragma unroll
        for (int j=0;j<4;j++)
            #pragma unroll
            for (int q=0;q<4;q++) acc[i][j][q]=0.0f;

    const int nk = K >> 4;   // BK=16

    // prefetch tile 0
    {
        float* as = As[0]; float* bs = Bs[0];
        cpasync16(as + aRow*ASTRIDE + aCol4,            Ag);
        cpasync16(as + (aRow+64)*ASTRIDE + aCol4,       Ag + (size_t)64*K);
        cpasync16(bs + bRow*BSTRIDE + bCol4,            Bg);
        cpasync16(bs + (bRow+8)*BSTRIDE + bCol4,        Bg + (size_t)8*N);
    }
    cp_commit();

    const int r  = lane >> 2;      // 0..7
    const int cc = lane & 3;       // 0..3

    for (int it=0; it<nk; it++){
        int cur = it & 1;
        if (it+1 < nk){
            int nxt = cur ^ 1;
            const float* Agn = Ag + (size_t)(it+1)*16;
            const float* Bgn = Bg + (size_t)(it+1)*16*N;
            float* as = As[nxt]; float* bs = Bs[nxt];
            cpasync16(as + aRow*ASTRIDE + aCol4,        Agn);
            cpasync16(as + (aRow+64)*ASTRIDE + aCol4,   Agn + (size_t)64*K);
            cpasync16(bs + bRow*BSTRIDE + bCol4,        Bgn);
            cpasync16(bs + (bRow+8)*BSTRIDE + bCol4,    Bgn + (size_t)8*N);
        }
        cp_commit();
        cp_wait<1>();
        __syncthreads();

        const float* as = As[cur];
        const float* bs = Bs[cur];
        #pragma unroll
        for (int ks=0; ks<2; ks++){
            uint32_t af[4][4];
            uint32_t bf[4][2];
            #pragma unroll
            for (int mi=0; mi<4; mi++){
                int base = (wm*64 + mi*16 + r)*ASTRIDE + ks*8 + cc;
                af[mi][0] = f2tf(as[base]);
                af[mi][1] = f2tf(as[base + 8*ASTRIDE]);
                af[mi][2] = f2tf(as[base + 4]);
                af[mi][3] = f2tf(as[base + 8*ASTRIDE + 4]);
            }
            #pragma unroll
            for (int ni=0; ni<4; ni++){
                int base = (ks*8 + cc)*BSTRIDE + wn*32 + ni*8 + r;
                bf[ni][0] = f2tf(bs[base]);
                bf[ni][1] = f2tf(bs[base + 4*BSTRIDE]);
            }
            #pragma unroll
            for (int mi=0; mi<4; mi++)
                #pragma unroll
                for (int ni=0; ni<4; ni++)
                    mma_tf32(acc[mi][ni], af[mi], bf[ni]);
        }
        __syncthreads();
    }

    // -------- epilogue --------
    #pragma unroll
    for (int mi=0; mi<4; mi++){
        int gr0 = by*128 + wm*64 + mi*16 + r;
        #pragma unroll
        for (int ni=0; ni<4; ni++){
            int col = bx*128 + wn*32 + ni*8 + cc*2;
            float b0 = bias[col], b1 = bias[col+1];
            #pragma unroll
            for (int half=0; half<2; half++){
                int row = gr0 + half*8;
                float v0 = acc[mi][ni][half*2+0] + b0;
                float v1 = acc[mi][ni][half*2+1] + b1;
                if (MODE==1){ v0 = v0/(1.0f+expf(-v0)); v1 = v1/(1.0f+expf(-v1)); }
                if (MODE==3){ v0 *= alpha; v1 *= alpha; }
                if (MODE==2){
                    const float2 rr = *(const float2*)(R + (size_t)row*N + col);
                    v0 = rr.x + alpha*v0; v1 = rr.y + alpha*v1;
                }
                *(float2*)(C + (size_t)row*N + col) = make_float2(v0, v1);
            }
        }
    }
}

// ---------------- banded attention: warp per (b,t,h); h += ctx in place ----------------
__global__ void attn_kernel(const float* __restrict__ Q, const float* __restrict__ Kt,
                            const float* __restrict__ V, float* __restrict__ Hh,
                            float* __restrict__ P){
    __shared__ float sc[8][WB+7];
    int warp = threadIdx.x >> 5;
    int lane = threadIdx.x & 31;
    int wg = blockIdx.x*8 + warp;          // 0 .. B*T*H-1
    int h = wg & (H-1);
    int t = (wg >> 3) & (T-1);
    int b = wg >> 13;
    size_t base = ((size_t)(b*T + t))*D + h*DH;
    int d0 = lane*2;
    float q0 = Q[base + d0], q1 = Q[base + d0 + 1];
    float* s = sc[warp];
    for (int w=0; w<WB; w++){
        int src = t - W1 + w;
        float sv = -1e9f;
        if ((unsigned)src < (unsigned)T){
            size_t kb = ((size_t)(b*T + src))*D + h*DH;
            float p = q0*Kt[kb+d0] + q1*Kt[kb+d0+1];
            #pragma unroll
            for (int o=16;o;o>>=1) p += __shfl_xor_sync(0xffffffffu, p, o);
            sv = p;
        }
        if (lane==0) s[w] = sv;
    }
    __syncwarp();
    float m = -1e30f;
    for (int w=lane; w<WB; w+=32) m = fmaxf(m, s[w]);
    #pragma unroll
    for (int o=16;o;o>>=1) m = fmaxf(m, __shfl_xor_sync(0xffffffffu, m, o));
    float sum = 0.0f;
    for (int w=lane; w<WB; w+=32){ float e = expf(s[w]-m); s[w]=e; sum+=e; }
    #pragma unroll
    for (int o=16;o;o>>=1) sum += __shfl_xor_sync(0xffffffffu, sum, o);
    float inv = 1.0f/sum;
    __syncwarp();
    float* pp = P + ((size_t)((b*T + t)*H + h))*WB;
    for (int w=lane; w<WB; w+=32) pp[w] = s[w]*inv;
    float a0=0.0f, a1=0.0f;
    for (int w=0; w<WB; w++){
        int src = t - W1 + w;
        if ((unsigned)src >= (unsigned)T) continue;
        float p = s[w]*inv;
        size_t vb = ((size_t)(b*T + src))*D + h*DH;
        a0 += p*V[vb+d0];
        a1 += p*V[vb+d0+1];
    }
    Hh[base+d0]   += a0;
    Hh[base+d0+1] += a1;
}

// ---------------- GLU: u = a * sigmoid(gate) ----------------
__global__ void glu_kernel(const float* __restrict__ CF, float* __restrict__ U){
    int idx = blockIdx.x*blockDim.x + threadIdx.x;     // NTOK*D
    int r = idx >> 9;
    int c = idx & (D-1);
    float a = CF[(size_t)r*CE + c];
    float g = CF[(size_t)r*CE + D + c];
    U[idx] = a / (1.0f + expf(-g));
}

// ---------------- depthwise conv (K=31) + bn + swish ----------------
__global__ void dwconv_kernel(const float* __restrict__ U, const float* __restrict__ Wd,
                              const float* __restrict__ bd, const float* __restrict__ bg,
                              const float* __restrict__ bb, float* __restrict__ O){
    int idx = blockIdx.x*blockDim.x + threadIdx.x;     // NTOK*D
    int c = idx & (D-1);
    int tt = idx >> 9;
    int t = tt & (T-1);
    int b = tt >> 10;
    float acc = bd[c];
    #pragma unroll
    for (int k=0;k<KS;k++){
        int src = t - (KS-1)/2 + k;
        if ((unsigned)src < (unsigned)T)
            acc = fmaf(U[((size_t)(b*T+src))*D + c], Wd[k*D + c], acc);
    }
    const float bns = 0.99999500003749937f;            // rsqrt(1+1e-5)
    acc = acc*bns*bg[c] + bb[c];
    O[idx] = acc / (1.0f + expf(-acc));                // swish
}

// ---------------- host ----------------
static float* symaddr(const void* s){
    void* p = nullptr;
    cudaGetSymbolAddress(&p, s);
    return (float*)p;
}

extern "C" void kernel_launch(void* const* d_in, const int* in_sizes, int n_in,
                              void* d_out, int out_size){
    const float* x         = (const float*)d_in[0];
    const float* ff1_ln_g  = (const float*)d_in[1];
    const float* ff1_ln_b  = (const float*)d_in[2];
    const float* ff1_w1    = (const float*)d_in[3];
    const float* ff1_b1    = (const float*)d_in[4];
    const float* ff1_w2    = (const float*)d_in[5];
    const float* ff1_b2    = (const float*)d_in[6];
    const float* ff2_ln_g  = (const float*)d_in[7];
    const float* ff2_ln_b  = (const float*)d_in[8];
    const float* ff2_w1    = (const float*)d_in[9];
    const float* ff2_b1    = (const float*)d_in[10];
    const float* ff2_w2    = (const float*)d_in[11];
    const float* ff2_b2    = (const float*)d_in[12];
    const float* wq        = (const float*)d_in[13];
    const float* bq        = (const float*)d_in[14];
    const float* wk        = (const float*)d_in[15];
    const float* bk        = (const float*)d_in[16];
    const float* wv        = (const float*)d_in[17];
    const float* bv        = (const float*)d_in[18];
    const float* conv_ln_g = (const float*)d_in[19];
    const float* conv_ln_b = (const float*)d_in[20];
    const float* pw1_w     = (const float*)d_in[21];
    const float* pw1_b     = (const float*)d_in[22];
    const float* dw_w      = (const float*)d_in[23];
    const float* dw_b      = (const float*)d_in[24];
    const float* bn_g      = (const float*)d_in[25];
    const float* bn_b      = (const float*)d_in[26];
    const float* pw2_w     = (const float*)d_in[27];
    const float* pw2_b     = (const float*)d_in[28];
    const float* fin_ln_g  = (const float*)d_in[29];
    const float* fin_ln_b  = (const float*)d_in[30];

    float* out   = (float*)d_out;
    float* probs = out + (size_t)NTOK*D;

    float* xln = symaddr(g_xln);
    float* ff  = symaddr(g_ff);
    float* h   = symaddr(g_h);
    float* q   = symaddr(g_q);
    float* k   = symaddr(g_k);
    float* v   = symaddr(g_v);
    float* cf  = symaddr(g_cf);
    float* u   = symaddr(g_u);
    float* v2  = symaddr(g_v2);

    const int M = NTOK;
    dim3 blk(256);

    // ---- ff1 (half-scale residual) ----
    ln_kernel<<<M,128>>>(x, ff1_ln_g, ff1_ln_b, xln);
    tgemm_kernel<1><<<dim3(FF/128, M/128), blk>>>(xln, ff1_w1, ff1_b1, nullptr, ff, M, FF, D, 1.0f);
    tgemm_kernel<2><<<dim3(D/128,  M/128), blk>>>(ff,  ff1_w2, ff1_b2, x,       h,  M, D, FF, 0.5f);

    // ---- QKV ----
    tgemm_kernel<3><<<dim3(D/128, M/128), blk>>>(h, wq, bq, nullptr, q, M, D, D, 0.125f); // 1/sqrt(64)
    tgemm_kernel<0><<<dim3(D/128, M/128), blk>>>(h, wk, bk, nullptr, k, M, D, D, 1.0f);
    tgemm_kernel<0><<<dim3(D/128, M/128), blk>>>(h, wv, bv, nullptr, v, M, D, D, 1.0f);

    // ---- banded attention (h += ctx in place; writes probs) ----
    attn_kernel<<<(Bx*T*H)/8, 256>>>(q, k, v, h, probs);

    // ---- conv module (residual in place) ----
    ln_kernel<<<M,128>>>(h, conv_ln_g, conv_ln_b, xln);
    tgemm_kernel<0><<<dim3(CE/128, M/128), blk>>>(xln, pw1_w, pw1_b, nullptr, cf, M, CE, D, 1.0f);
    glu_kernel<<<(NTOK*D)/256, 256>>>(cf, u);
    dwconv_kernel<<<(NTOK*D)/256, 256>>>(u, dw_w, dw_b, bn_g, bn_b, v2);
    tgemm_kernel<2><<<dim3(D/128, M/128), blk>>>(v2, pw2_w, pw2_b, h, h, M, D, D, 1.0f);

    // ---- ff2 (half-scale residual, in place) ----
    ln_kernel<<<M,128>>>(h, ff2_ln_g, ff2_ln_b, xln);
    tgemm_kernel<1><<<dim3(FF/128, M/128), blk>>>(xln, ff2_w1, ff2_b1, nullptr, ff, M, FF, D, 1.0f);
    tgemm_kernel<2><<<dim3(D/128,  M/128), blk>>>(ff,  ff2_w2, ff2_b2, h,       h,  M, D, FF, 0.5f);

    // ---- final LN straight into d_out ----
    ln_kernel<<<M,128>>>(h, fin_ln_g, fin_ln_b, out);
}